// round 17
// baseline (speedup 1.0000x reference)
#include <cuda_runtime.h>
#include <cstdint>

// ============================================================================
// SpikingReservoirLoaded: B=64, T=500, R=2048, beta=0.9, thr=1.0, zero reset.
//   V_t = beta*V_{t-1} + x[b,t]*w_in[r] + sum_{j: S_{t-1}[b,j]=1} W[j,r]
//
// R16 = R15 with the smem-crossbar conflict tax removed:
//  * W rows stored at 80B stride: j*80 mod 128 cycles 8 bank classes
//    (64B stride had only 2 -> ~1.3x wavefront tax). Row data still 64B.
//  * index lists are 1-byte ascending DELTAS (gap<=255 w.h.p.), 1024/batch,
//    freeing the smem for the 80B stride. Decoder keeps a running cursor;
//    add order = strict ascending j, single f32x2 accumulators -> bit-exact.
//  * exact fallback: batches with n<=512, n>1024, or any delta>255
//    (ballot-detected) use absolute uint16 format (+ global overflow).
// Unchanged: 768 thr, 256 gatherers (64 b x 4 quads, LDS.128), 24-warp
// build, flag-array barrier, scalar record stores.
// ============================================================================

#define T_STEPS   500
#define BATCH     64
#define NWORDS32  64
#define RSIZE     2048
#define NBLOCKS   128
#define NTHREADS  768
#define GATHER_T  256
#define TBR       (500LL * 64LL * 2048LL)

#define WSTRIDE   80                      // bytes per W row in smem
#define CAP_BYTES 1024                    // list bytes per batch (1024 deltas / 512 shorts)
#define SHORT_CAP 512
#define OVF_CAP   1280
#define SMEM_W_BYTES   (RSIZE * WSTRIDE)              // 163840
#define SMEM_IDX_OFF   (SMEM_W_BYTES)                 // 1024-aligned
#define SMEM_CNT_OFF   (SMEM_IDX_OFF + BATCH * CAP_BYTES)   // 229376
#define SMEM_BYTES     (SMEM_CNT_OFF + BATCH * 4)           // 229632

__device__ unsigned g_masks[2][BATCH][NWORDS32];
__device__ unsigned g_flags[NBLOCKS];
__device__ unsigned long long g_spike_count;
__device__ unsigned short g_ovf[NBLOCKS][BATCH][OVF_CAP];

__global__ void snn_init_kernel() {
    int t = threadIdx.x;
    for (int i = t; i < BATCH * NWORDS32; i += blockDim.x)
        (&g_masks[0][0][0])[i] = 0u;               // S0 = 0
    if (t < NBLOCKS) g_flags[t] = 0u;
    if (t == 0) g_spike_count = 0ull;
}

__device__ __forceinline__ void st_release_gpu(unsigned* p, unsigned v) {
    asm volatile("st.release.gpu.global.u32 [%0], %1;" :: "l"(p), "r"(v) : "memory");
}
__device__ __forceinline__ unsigned ld_acquire_gpu(const unsigned* p) {
    unsigned v;
    asm volatile("ld.acquire.gpu.global.u32 %0, [%1];" : "=r"(v) : "l"(p) : "memory");
    return v;
}
__device__ __forceinline__ unsigned long long add_f32x2(unsigned long long a,
                                                        unsigned long long b) {
    unsigned long long r;
    asm("add.rn.f32x2 %0, %1, %2;" : "=l"(r) : "l"(a), "l"(b));
    return r;
}

__global__ void __launch_bounds__(NTHREADS, 1)
snn_kernel(const float* __restrict__ x,
           const float* __restrict__ w_in,
           const float* __restrict__ W,
           float* __restrict__ spike_out,    // 4B-aligned only!
           float* __restrict__ mem_out,      // 4B-aligned only!
           float* avg_out)
{
    extern __shared__ char smem[];
    unsigned char* sidx = reinterpret_cast<unsigned char*>(smem + SMEM_IDX_OFF);
    int* scnt = reinterpret_cast<int*>(smem + SMEM_CNT_OFF);

    const int tid  = threadIdx.x;
    const int cta  = blockIdx.x;
    const int lane = tid & 31;
    const int warp = tid >> 5;
    const bool gatherer = (tid < GATHER_T);
    const int b    = gatherer ? (tid >> 2) : 0;
    const int q    = tid & 3;
    const int col0 = cta * 16 + q * 4;

    // ---- load W column slice into smem at 80B row stride ----
    for (int idx = tid; idx < RSIZE * 8; idx += NTHREADS) {
        int j = idx >> 3, qq = idx & 7;
        float2 v = *reinterpret_cast<const float2*>(W + (size_t)j * RSIZE + cta * 16 + qq * 2);
        *reinterpret_cast<float2*>(smem + j * WSTRIDE + qq * 8) = v;
    }

    const float4 win4 = *reinterpret_cast<const float4*>(w_in + col0);
    const float* __restrict__ xb = x + b * T_STEPS;
    const char* wbase = smem + (q << 4);   // + j*80 gives this quad's 16B

    float4 V = make_float4(0.f, 0.f, 0.f, 0.f);
    unsigned cnt = 0;
    const long long recBase = (long long)b * RSIZE + col0;
    const int nb = (warp < 16) ? 3 : 2;

    for (int t = 0; t < T_STEPS; ++t) {
        // ================= build lists (24 warps, 2-3 batches each) =========
        {
            const unsigned* gm = &g_masks[t & 1][0][0];
            #pragma unroll
            for (int qq = 0; qq < 3; ++qq) {
                if (qq >= nb) break;
                const int bq = warp + qq * 24;
                const unsigned* mb = gm + bq * NWORDS32;
                unsigned w0 = __ldcg(mb + lane);
                unsigned w1 = __ldcg(mb + 32 + lane);
                int c0 = __popc(w0), c1 = __popc(w1);
                int s0 = c0, s1 = c1;
                #pragma unroll
                for (int d = 1; d < 32; d <<= 1) {
                    int u0 = __shfl_up_sync(0xffffffffu, s0, d);
                    int u1 = __shfl_up_sync(0xffffffffu, s1, d);
                    if (lane >= d) { s0 += u0; s1 += u1; }
                }
                int tot0 = __shfl_sync(0xffffffffu, s0, 31);
                int n = tot0 + __shfl_sync(0xffffffffu, s1, 31);

                // last-set-j per lane + inclusive max-scans (for delta prevs)
                int jb0 = lane * 32, jb1 = 1024 + lane * 32;
                int m0 = w0 ? (jb0 + 31 - __clz(w0)) : -1;
                #pragma unroll
                for (int d = 1; d < 32; d <<= 1) {
                    int u = __shfl_up_sync(0xffffffffu, m0, d);
                    if (lane >= d) m0 = (u > m0) ? u : m0;
                }
                int carry1 = __shfl_sync(0xffffffffu, m0, 31);
                int m1 = w1 ? (jb1 + 31 - __clz(w1)) : -1;
                if (lane == 0 && carry1 > m1) m1 = carry1;
                #pragma unroll
                for (int d = 1; d < 32; d <<= 1) {
                    int u = __shfl_up_sync(0xffffffffu, m1, d);
                    if (lane >= d) m1 = (u > m1) ? u : m1;
                }
                int p0 = __shfl_up_sync(0xffffffffu, m0, 1); if (lane == 0) p0 = -1;
                int p1 = __shfl_up_sync(0xffffffffu, m1, 1); if (lane == 0) p1 = carry1;

                bool fmtShort = (n <= SHORT_CAP) || (n > CAP_BYTES);
                bool bad = false;
                if (!fmtShort) {
                    unsigned char* L = sidx + bq * CAP_BYTES;
                    int pos = s0 - c0, pj = p0;
                    unsigned m = w0;
                    while (m) {
                        int j = jb0 + __ffs(m) - 1; m &= m - 1;
                        int d = j - pj; if (d > 255) { bad = true; d = 255; }
                        L[pos] = (unsigned char)d; pj = j; ++pos;
                    }
                    pos = tot0 + s1 - c1; pj = p1; m = w1;
                    while (m) {
                        int j = jb1 + __ffs(m) - 1; m &= m - 1;
                        int d = j - pj; if (d > 255) { bad = true; d = 255; }
                        L[pos] = (unsigned char)d; pj = j; ++pos;
                    }
                    bad = (__ballot_sync(0xffffffffu, bad) != 0u);
                }
                if (fmtShort || bad) {       // exact fallback: absolute uint16
                    fmtShort = true;
                    unsigned short* L16 = reinterpret_cast<unsigned short*>(sidx + bq * CAP_BYTES);
                    unsigned short* G = &g_ovf[cta][bq][0];
                    int pos = s0 - c0; unsigned m = w0;
                    while (m) {
                        int j = jb0 + __ffs(m) - 1; m &= m - 1;
                        if (pos < SHORT_CAP) L16[pos] = (unsigned short)j;
                        else                 G[pos - SHORT_CAP] = (unsigned short)j;
                        ++pos;
                    }
                    pos = tot0 + s1 - c1; m = w1;
                    while (m) {
                        int j = jb1 + __ffs(m) - 1; m &= m - 1;
                        if (pos < SHORT_CAP) L16[pos] = (unsigned short)j;
                        else                 G[pos - SHORT_CAP] = (unsigned short)j;
                        ++pos;
                    }
                }
                if (lane == 0) scnt[bq] = n | (fmtShort ? 0x10000 : 0);
            }
        }
        __syncthreads();

        bool s0b = false, s1b = false, s2b = false, s3b = false;
        if (gatherer) {
            float xv = __ldg(xb + t);
            unsigned long long acc01 = 0ull, acc23 = 0ull;
            int info = scnt[b];
            int n = info & 0xFFFF;
            if (!(info & 0x10000)) {
                // ---- byte-delta path: running cursor, ascending j ----
                const unsigned char* L = sidx + b * CAP_BYTES;
                const uint2* L8 = reinterpret_cast<const uint2*>(L);
                int trips = n >> 3;
                int co = -WSTRIDE;
                #pragma unroll 1
                for (int i = 0; i < trips; ++i) {
                    uint2 v = L8[i];
                    unsigned d0 = v.x & 255u, d1 = (v.x >> 8) & 255u;
                    unsigned d2 = (v.x >> 16) & 255u, d3 = v.x >> 24;
                    unsigned d4 = v.y & 255u, d5 = (v.y >> 8) & 255u;
                    unsigned d6 = (v.y >> 16) & 255u, d7 = v.y >> 24;
                    int a0 = co + (int)d0 * WSTRIDE;
                    int a1 = a0 + (int)d1 * WSTRIDE;
                    int a2 = a1 + (int)d2 * WSTRIDE;
                    int a3 = a2 + (int)d3 * WSTRIDE;
                    int a4 = a3 + (int)d4 * WSTRIDE;
                    int a5 = a4 + (int)d5 * WSTRIDE;
                    int a6 = a5 + (int)d6 * WSTRIDE;
                    int a7 = a6 + (int)d7 * WSTRIDE;
                    co = a7;
                    ulonglong2 r0 = *reinterpret_cast<const ulonglong2*>(wbase + a0);
                    ulonglong2 r1 = *reinterpret_cast<const ulonglong2*>(wbase + a1);
                    ulonglong2 r2 = *reinterpret_cast<const ulonglong2*>(wbase + a2);
                    ulonglong2 r3 = *reinterpret_cast<const ulonglong2*>(wbase + a3);
                    ulonglong2 r4 = *reinterpret_cast<const ulonglong2*>(wbase + a4);
                    ulonglong2 r5 = *reinterpret_cast<const ulonglong2*>(wbase + a5);
                    ulonglong2 r6 = *reinterpret_cast<const ulonglong2*>(wbase + a6);
                    ulonglong2 r7 = *reinterpret_cast<const ulonglong2*>(wbase + a7);
                    acc01 = add_f32x2(acc01, r0.x); acc23 = add_f32x2(acc23, r0.y);
                    acc01 = add_f32x2(acc01, r1.x); acc23 = add_f32x2(acc23, r1.y);
                    acc01 = add_f32x2(acc01, r2.x); acc23 = add_f32x2(acc23, r2.y);
                    acc01 = add_f32x2(acc01, r3.x); acc23 = add_f32x2(acc23, r3.y);
                    acc01 = add_f32x2(acc01, r4.x); acc23 = add_f32x2(acc23, r4.y);
                    acc01 = add_f32x2(acc01, r5.x); acc23 = add_f32x2(acc23, r5.y);
                    acc01 = add_f32x2(acc01, r6.x); acc23 = add_f32x2(acc23, r6.y);
                    acc01 = add_f32x2(acc01, r7.x); acc23 = add_f32x2(acc23, r7.y);
                }
                #pragma unroll 1
                for (int k = trips << 3; k < n; ++k) {
                    co += (int)L[k] * WSTRIDE;
                    ulonglong2 r = *reinterpret_cast<const ulonglong2*>(wbase + co);
                    acc01 = add_f32x2(acc01, r.x);
                    acc23 = add_f32x2(acc23, r.y);
                }
            } else {
                // ---- absolute uint16 path (early steps / fallback) ----
                const unsigned short* L16 =
                    reinterpret_cast<const unsigned short*>(sidx + b * CAP_BYTES);
                int ns = n < SHORT_CAP ? n : SHORT_CAP;
                int n4 = ns & ~3;
                const uint2* L2 = reinterpret_cast<const uint2*>(L16);
                #pragma unroll 1
                for (int i = 0; i < n4; i += 4) {
                    uint2 v = L2[i >> 2];
                    int j0 = v.x & 0xFFFF, j1 = v.x >> 16;
                    int j2 = v.y & 0xFFFF, j3 = v.y >> 16;
                    ulonglong2 r0 = *reinterpret_cast<const ulonglong2*>(wbase + j0 * WSTRIDE);
                    ulonglong2 r1 = *reinterpret_cast<const ulonglong2*>(wbase + j1 * WSTRIDE);
                    ulonglong2 r2 = *reinterpret_cast<const ulonglong2*>(wbase + j2 * WSTRIDE);
                    ulonglong2 r3 = *reinterpret_cast<const ulonglong2*>(wbase + j3 * WSTRIDE);
                    acc01 = add_f32x2(acc01, r0.x); acc23 = add_f32x2(acc23, r0.y);
                    acc01 = add_f32x2(acc01, r1.x); acc23 = add_f32x2(acc23, r1.y);
                    acc01 = add_f32x2(acc01, r2.x); acc23 = add_f32x2(acc23, r2.y);
                    acc01 = add_f32x2(acc01, r3.x); acc23 = add_f32x2(acc23, r3.y);
                }
                #pragma unroll 1
                for (int k = n4; k < ns; ++k) {
                    ulonglong2 r = *reinterpret_cast<const ulonglong2*>(
                        wbase + (int)L16[k] * WSTRIDE);
                    acc01 = add_f32x2(acc01, r.x);
                    acc23 = add_f32x2(acc23, r.y);
                }
                #pragma unroll 1
                for (int k = SHORT_CAP; k < n; ++k) {   // global overflow (never-path)
                    ulonglong2 r = *reinterpret_cast<const ulonglong2*>(
                        wbase + (int)g_ovf[cta][b][k - SHORT_CAP] * WSTRIDE);
                    acc01 = add_f32x2(acc01, r.x);
                    acc23 = add_f32x2(acc23, r.y);
                }
            }
            float a0 = __uint_as_float((unsigned)(acc01 & 0xffffffffull));
            float a1 = __uint_as_float((unsigned)(acc01 >> 32));
            float a2 = __uint_as_float((unsigned)(acc23 & 0xffffffffull));
            float a3 = __uint_as_float((unsigned)(acc23 >> 32));

            float v0 = fmaf(0.9f, V.x, xv * win4.x) + a0;
            float v1 = fmaf(0.9f, V.y, xv * win4.y) + a1;
            float v2 = fmaf(0.9f, V.z, xv * win4.z) + a2;
            float v3 = fmaf(0.9f, V.w, xv * win4.w) + a3;
            s0b = (v0 >= 1.0f); s1b = (v1 >= 1.0f);
            s2b = (v2 >= 1.0f); s3b = (v3 >= 1.0f);
            V.x = s0b ? 0.f : v0;
            V.y = s1b ? 0.f : v1;
            V.z = s2b ? 0.f : v2;
            V.w = s3b ? 0.f : v3;
            cnt += (unsigned)s0b + (unsigned)s1b + (unsigned)s2b + (unsigned)s3b;

            unsigned hv = ((unsigned)s0b | ((unsigned)s1b << 1) |
                           ((unsigned)s2b << 2) | ((unsigned)s3b << 3)) << (q * 4);
            hv |= __shfl_xor_sync(0xffffffffu, hv, 1);
            hv |= __shfl_xor_sync(0xffffffffu, hv, 2);
            if (q == 0) {
                unsigned short* m16 =
                    reinterpret_cast<unsigned short*>(&g_masks[(t + 1) & 1][0][0]);
                m16[b * 128 + cta] = (unsigned short)hv;
            }
        }

        // ---- chip barrier: parallel flag array ----
        __syncthreads();
        if (tid == 0) st_release_gpu(&g_flags[cta], (unsigned)(t + 1));
        if (gatherer && spike_out) {
            long long off = (long long)t * (BATCH * RSIZE) + recBase;
            spike_out[off]     = s0b ? 1.f : 0.f;
            spike_out[off + 1] = s1b ? 1.f : 0.f;
            spike_out[off + 2] = s2b ? 1.f : 0.f;
            spike_out[off + 3] = s3b ? 1.f : 0.f;
            mem_out[off]     = V.x;
            mem_out[off + 1] = V.y;
            mem_out[off + 2] = V.z;
            mem_out[off + 3] = V.w;
        }
        if (tid < NBLOCKS) {
            while (ld_acquire_gpu(&g_flags[tid]) < (unsigned)(t + 1)) { }
        }
        __syncthreads();
    }

    #pragma unroll
    for (int s = 16; s; s >>= 1)
        cnt += __shfl_down_sync(0xffffffffu, cnt, s);
    if (lane == 0 && cnt) atomicAdd(&g_spike_count, (unsigned long long)cnt);

    __syncthreads();
    if (tid == 0) st_release_gpu(&g_flags[cta], (unsigned)(T_STEPS + 1));

    if (cta == 0) {
        if (tid < NBLOCKS) {
            while (ld_acquire_gpu(&g_flags[tid]) < (unsigned)(T_STEPS + 1)) { }
        }
        __syncthreads();
        if (tid == 0 && avg_out) {
            double c = (double)g_spike_count;
            *avg_out = (float)(c / (double)TBR);
        }
    }
}

extern "C" void kernel_launch(void* const* d_in, const int* in_sizes, int n_in,
                              void* d_out, int out_size) {
    (void)in_sizes; (void)n_in;
    const float* x    = (const float*)d_in[0];
    const float* w_in = (const float*)d_in[1];
    const float* W    = (const float*)d_in[2];
    float* out = (float*)d_out;

    float* spike = nullptr;
    float* mem   = nullptr;
    float* avg   = nullptr;
    const long long tbr = TBR;
    const long long osz = (long long)out_size;

    if (osz == 2 * tbr + 1) {
        avg = out; spike = out + 1; mem = out + 1 + tbr;
    } else if (osz == 2 * tbr) {
        spike = out; mem = out + tbr;
    } else if (osz == 1) {
        avg = out;
    } else if (osz > 2 * tbr + 1) {
        avg = out; spike = out + 1; mem = out + 1 + tbr;
    } else {
        avg = out;
    }

    static int smem_set = 0;
    if (!smem_set) {
        cudaFuncSetAttribute(snn_kernel,
                             cudaFuncAttributeMaxDynamicSharedMemorySize, SMEM_BYTES);
        smem_set = 1;
    }

    snn_init_kernel<<<1, 256>>>();
    snn_kernel<<<NBLOCKS, NTHREADS, SMEM_BYTES>>>(x, w_in, W, spike, mem, avg);
}